// round 1
// baseline (speedup 1.0000x reference)
#include <cuda_runtime.h>
#include <math.h>

// ---------------- problem constants ----------------
#define BS    32
#define LQ    300
#define NH    8
#define HD    32
#define EMB   (NH*HD)        // 256
#define NLVL  4
#define NPTS  4
#define SUMP  (NLVL*NPTS)    // 16
#define TOTAL 8500
#define NCOLS (EMB + NH*SUMP) // 256 off cols + 128 attn cols = 384
#define MROWS (BS*LQ)        // 9600

__device__ __constant__ int c_lvl_start[NLVL] = {0, 6400, 8000, 8400};
__device__ __constant__ int c_lvl_H[NLVL]     = {80, 40, 20, 10};
__device__ __constant__ int c_lvl_W[NLVL]     = {80, 40, 20, 10};

// ---------------- scratch (no allocation allowed) ----------------
__device__ float g_valueT[(size_t)BS*NH*TOTAL*HD];     // ~278 MB, [b,h,s,d]
__device__ float g_attn[(size_t)MROWS*NH*SUMP];        // softmaxed attn weights
__device__ float g_loc[(size_t)MROWS*NH*SUMP*2];       // normalized [0,1] sample locs

// ================= kernel 1: value transpose =================
// value [b,h,d=32, s=8500]  ->  g_valueT [b,h,s,d]
__global__ __launch_bounds__(256) void k_transpose(const float* __restrict__ value) {
    __shared__ float tile[32][33];
    int bh = blockIdx.y;                 // 0..255
    int s0 = blockIdx.x * 32;
    int tx = threadIdx.x;                // 0..31 (s within tile on read)
    int ty = threadIdx.y;                // 0..7

    const float* src = value + (size_t)bh * HD * TOTAL;
    float* dst = g_valueT + (size_t)bh * TOTAL * HD;

    int s = s0 + tx;
    if (s < TOTAL) {
        #pragma unroll
        for (int i = 0; i < 4; i++) {
            int d = ty + i * 8;
            tile[d][tx] = src[(size_t)d * TOTAL + s];
        }
    }
    __syncthreads();
    #pragma unroll
    for (int i = 0; i < 4; i++) {
        int sl = ty + i * 8;
        int ss = s0 + sl;
        if (ss < TOTAL) {
            dst[(size_t)ss * HD + tx] = tile[tx][sl];
        }
    }
}

// ================= kernel 2: projections + softmax + locations =================
// One block = 32 query rows, 384 threads (thread n = output column n).
// cols 0..255  -> offsets (h = n/32, p = (n%32)/2, comp = n%2)
// cols 256..383-> attn logits (j = n-256, h = j/16, p = j%16), softmaxed over p.
__global__ __launch_bounds__(384) void k_proj(const float* __restrict__ query,
                                              const float* __restrict__ refpts,
                                              const float* __restrict__ W_off,
                                              const float* __restrict__ b_off,
                                              const float* __restrict__ W_attn,
                                              const float* __restrict__ b_attn) {
    __shared__ float qs[32 * EMB];   // 32 KB
    int m0 = blockIdx.x * 32;
    int n  = threadIdx.x;

    // load 32 query rows (contiguous: query is [9600][256])
    for (int idx = n; idx < 32 * EMB; idx += 384)
        qs[idx] = query[(size_t)m0 * EMB + idx];
    __syncthreads();

    float acc[32];
    #pragma unroll
    for (int i = 0; i < 32; i++) acc[i] = 0.f;

    const bool is_off = (n < EMB);
    const float* Wcol_base = is_off ? W_off : W_attn;
    const int    Wld       = is_off ? EMB   : NH*SUMP;
    const int    ncol      = is_off ? n     : n - EMB;

    for (int k = 0; k < EMB; k++) {
        float w = Wcol_base[(size_t)k * Wld + ncol];
        const float* qk = qs + k;
        #pragma unroll
        for (int i = 0; i < 32; i++)
            acc[i] = fmaf(qk[i * EMB], w, acc[i]);
    }

    if (is_off) {
        // offsets -> sampling locations
        int h    = n >> 5;
        int rem  = n & 31;
        int p    = rem >> 1;
        int comp = rem & 1;
        float bias = b_off[n];
        #pragma unroll 4
        for (int i = 0; i < 32; i++) {
            int gm = m0 + i;
            float rxy = refpts[(size_t)gm * 4 + comp];
            float rwh = refpts[(size_t)gm * 4 + 2 + comp];
            float off = acc[i] + bias;
            float loc = rxy + off * (1.0f / NPTS) * rwh * 0.5f;
            g_loc[(((size_t)gm * NH + h) * SUMP + p) * 2 + comp] = loc;
        }
    } else {
        // attn logits -> softmax over 16 points (16-lane warp groups)
        int j = n - EMB;
        int h = j >> 4;
        int p = j & 15;
        float bias = b_attn[j];
        #pragma unroll 2
        for (int i = 0; i < 32; i++) {
            float v = acc[i] + bias;
            float mx = v;
            #pragma unroll
            for (int o = 8; o > 0; o >>= 1)
                mx = fmaxf(mx, __shfl_xor_sync(0xffffffffu, mx, o, 16));
            float e = __expf(v - mx);
            float s = e;
            #pragma unroll
            for (int o = 8; o > 0; o >>= 1)
                s += __shfl_xor_sync(0xffffffffu, s, o, 16);
            int gm = m0 + i;
            g_attn[((size_t)gm * NH + h) * SUMP + p] = e / s;
        }
    }
}

// ================= kernel 3: bilinear sampling + weighted sum =================
// One warp per (b,h,q), lane = channel d. Warps ordered (b,h,q) for L2 locality.
__global__ __launch_bounds__(256) void k_sample(float* __restrict__ out) {
    int warp = blockIdx.x * 8 + (threadIdx.x >> 5);
    int d    = threadIdx.x & 31;
    if (warp >= BS * NH * LQ) return;

    int q  = warp % LQ;
    int bh = warp / LQ;       // b*NH + h
    int b  = bh / NH;
    int h  = bh % NH;
    int gm = b * LQ + q;

    const float* vt = g_valueT + (size_t)bh * TOTAL * HD;
    const float* locp  = g_loc  + ((size_t)gm * NH + h) * SUMP * 2;
    const float* attnp = g_attn + ((size_t)gm * NH + h) * SUMP;

    float acc = 0.f;
    #pragma unroll
    for (int p = 0; p < SUMP; p++) {
        int lvl = p >> 2;
        int Hh = c_lvl_H[lvl], Ww = c_lvl_W[lvl];
        int st = c_lvl_start[lvl];
        float a  = attnp[p];
        float lx = locp[p * 2 + 0];
        float ly = locp[p * 2 + 1];
        // grid = 2*loc-1; pixel = (grid+1)*0.5*W - 0.5 = loc*W - 0.5
        float x = lx * (float)Ww - 0.5f;
        float y = ly * (float)Hh - 0.5f;
        float fx0 = floorf(x), fy0 = floorf(y);
        int ix0 = (int)fx0, iy0 = (int)fy0;
        float fx = x - fx0, fy = y - fy0;
        int ix1 = ix0 + 1, iy1 = iy0 + 1;

        bool vx0 = (ix0 >= 0) & (ix0 < Ww);
        bool vx1 = (ix1 >= 0) & (ix1 < Ww);
        bool vy0 = (iy0 >= 0) & (iy0 < Hh);
        bool vy1 = (iy1 >= 0) & (iy1 < Hh);

        float v00 = (vx0 & vy0) ? vt[(size_t)(st + iy0 * Ww + ix0) * HD + d] : 0.f;
        float v10 = (vx1 & vy0) ? vt[(size_t)(st + iy0 * Ww + ix1) * HD + d] : 0.f;
        float v01 = (vx0 & vy1) ? vt[(size_t)(st + iy1 * Ww + ix0) * HD + d] : 0.f;
        float v11 = (vx1 & vy1) ? vt[(size_t)(st + iy1 * Ww + ix1) * HD + d] : 0.f;

        float bil = v00 * (1.f - fx) * (1.f - fy)
                  + v10 * fx * (1.f - fy)
                  + v01 * (1.f - fx) * fy
                  + v11 * fx * fy;
        acc = fmaf(a, bil, acc);
    }
    out[(size_t)gm * EMB + h * HD + d] = acc;
}

// ================= launch =================
extern "C" void kernel_launch(void* const* d_in, const int* in_sizes, int n_in,
                              void* d_out, int out_size) {
    const float* query  = (const float*)d_in[0];
    const float* refpts = (const float*)d_in[1];
    const float* value  = (const float*)d_in[2];
    // d_in[3] = value_spatial_shapes (int32) -- constants hardcoded
    const float* W_off  = (const float*)d_in[4];
    const float* b_off  = (const float*)d_in[5];
    const float* W_attn = (const float*)d_in[6];
    const float* b_attn = (const float*)d_in[7];
    float* out = (float*)d_out;

    dim3 tgrid((TOTAL + 31) / 32, BS * NH);
    k_transpose<<<tgrid, dim3(32, 8)>>>(value);

    k_proj<<<MROWS / 32, 384>>>(query, refpts, W_off, b_off, W_attn, b_attn);

    int nwarps = BS * NH * LQ;                // 76800
    k_sample<<<(nwarps + 7) / 8, 256>>>(out);
}

// round 2
// speedup vs baseline: 1.2239x; 1.2239x over previous
#include <cuda_runtime.h>
#include <cuda_fp16.h>
#include <math.h>

// ---------------- problem constants ----------------
#define BS    32
#define LQ    300
#define NH    8
#define HD    32
#define EMB   (NH*HD)        // 256
#define NLVL  4
#define NPTS  4
#define SUMP  (NLVL*NPTS)    // 16
#define TOTAL 8500
#define MROWS (BS*LQ)        // 9600

__device__ __constant__ int c_lvl_start[NLVL] = {0, 6400, 8000, 8400};
__device__ __constant__ int c_lvl_H[NLVL]     = {80, 40, 20, 10};
__device__ __constant__ int c_lvl_W[NLVL]     = {80, 40, 20, 10};

// ---------------- scratch (no allocation allowed) ----------------
__device__ __half g_valueT[(size_t)BS*NH*TOTAL*HD];    // ~139 MB, [b,h,s,d] fp16
__device__ float  g_attn[(size_t)MROWS*NH*SUMP];       // softmaxed attn weights
__device__ float  g_loc[(size_t)MROWS*NH*SUMP*2];      // normalized [0,1] sample locs

// ---------------- f32x2 packed helpers (sm_103a) ----------------
__device__ __forceinline__ unsigned long long pack_f32x2(float lo, float hi) {
    unsigned long long r;
    asm("mov.b64 %0, {%1, %2};" : "=l"(r) : "f"(lo), "f"(hi));
    return r;
}
__device__ __forceinline__ void unpack_f32x2(unsigned long long v, float& lo, float& hi) {
    asm("mov.b64 {%0, %1}, %2;" : "=f"(lo), "=f"(hi) : "l"(v));
}
__device__ __forceinline__ void ffma2(unsigned long long& d, unsigned long long a, unsigned long long b) {
    asm("fma.rn.f32x2 %0, %1, %2, %0;" : "+l"(d) : "l"(a), "l"(b));
}

// ================= kernel 1: value transpose fp32 [b,h,d,s] -> fp16 [b,h,s,d] =================
__global__ __launch_bounds__(256) void k_transpose(const float* __restrict__ value) {
    __shared__ float tile[32][33];
    int bh = blockIdx.y;                 // 0..255
    int s0 = blockIdx.x * 32;
    int t  = threadIdx.x;
    int tx = t & 31;                     // s within tile on read
    int ty = t >> 5;                     // 0..7

    const float* src = value + (size_t)bh * HD * TOTAL;
    __half* dst = g_valueT + (size_t)bh * TOTAL * HD;

    int s = s0 + tx;
    if (s < TOTAL) {
        #pragma unroll
        for (int i = 0; i < 4; i++) {
            int d = ty + i * 8;
            tile[d][tx] = src[(size_t)d * TOTAL + s];
        }
    }
    __syncthreads();
    // write side: 32 rows x 16 half2 = 512 half2; 256 threads x 2
    #pragma unroll
    for (int j = 0; j < 2; j++) {
        int e  = t + j * 256;
        int sl = e >> 4;     // local s row 0..31
        int dp = e & 15;     // half2 index (d pair)
        int ss = s0 + sl;
        if (ss < TOTAL) {
            __half2 v = __floats2half2_rn(tile[2*dp][sl], tile[2*dp + 1][sl]);
            *((__half2*)(dst + (size_t)ss * HD) + dp) = v;
        }
    }
}

// ================= kernel 2: projections + softmax + locations =================
// One block = 32 query rows, 384 threads (thread n = output column n).
// cols 0..255  -> offsets (h = n/32, p = (n%32)/2, comp = n%2)
// cols 256..383-> attn logits (j = n-256, h = j/16, p = j%16), softmaxed over p.
__global__ __launch_bounds__(384) void k_proj(const float* __restrict__ query,
                                              const float* __restrict__ refpts,
                                              const float* __restrict__ W_off,
                                              const float* __restrict__ b_off,
                                              const float* __restrict__ W_attn,
                                              const float* __restrict__ b_attn) {
    __shared__ float qs[32 * EMB];   // 32 KB, [row][k]
    int m0 = blockIdx.x * 32;
    int n  = threadIdx.x;

    for (int idx = n; idx < 32 * EMB; idx += 384)
        qs[idx] = query[(size_t)m0 * EMB + idx];
    __syncthreads();

    const bool  is_off    = (n < EMB);
    const float* Wcol     = is_off ? W_off : W_attn;
    const int    Wld      = is_off ? EMB   : NH*SUMP;
    const int    ncol     = is_off ? n     : n - EMB;

    // packed f32x2 accumulators: lanes = (even-k partial, odd-k partial)
    unsigned long long acc2[32];
    #pragma unroll
    for (int i = 0; i < 32; i++) acc2[i] = 0ull;

    #pragma unroll 2
    for (int k = 0; k < EMB; k += 2) {
        float w0 = Wcol[(size_t)k       * Wld + ncol];
        float w1 = Wcol[(size_t)(k + 1) * Wld + ncol];
        unsigned long long w2 = pack_f32x2(w0, w1);
        const unsigned long long* q2p =
            (const unsigned long long*)(qs + k);
        #pragma unroll
        for (int i = 0; i < 32; i++)
            ffma2(acc2[i], q2p[i * (EMB / 2)], w2);
    }

    if (is_off) {
        int h    = n >> 5;
        int rem  = n & 31;
        int p    = rem >> 1;
        int comp = rem & 1;
        float bias = b_off[n];
        #pragma unroll 4
        for (int i = 0; i < 32; i++) {
            float lo, hi; unpack_f32x2(acc2[i], lo, hi);
            int gm = m0 + i;
            float rxy = refpts[(size_t)gm * 4 + comp];
            float rwh = refpts[(size_t)gm * 4 + 2 + comp];
            float off = lo + hi + bias;
            float loc = rxy + off * (1.0f / NPTS) * rwh * 0.5f;
            g_loc[(((size_t)gm * NH + h) * SUMP + p) * 2 + comp] = loc;
        }
    } else {
        int j = n - EMB;
        int h = j >> 4;
        int p = j & 15;
        float bias = b_attn[j];
        #pragma unroll 2
        for (int i = 0; i < 32; i++) {
            float lo, hi; unpack_f32x2(acc2[i], lo, hi);
            float v = lo + hi + bias;
            float mx = v;
            #pragma unroll
            for (int o = 8; o > 0; o >>= 1)
                mx = fmaxf(mx, __shfl_xor_sync(0xffffffffu, mx, o, 16));
            float e = __expf(v - mx);
            float sum = e;
            #pragma unroll
            for (int o = 8; o > 0; o >>= 1)
                sum += __shfl_xor_sync(0xffffffffu, sum, o, 16);
            int gm = m0 + i;
            g_attn[((size_t)gm * NH + h) * SUMP + p] = e / sum;
        }
    }
}

// ================= kernel 3: bilinear sampling + weighted sum =================
// One warp per (b,h,q), lane = channel d. Warps ordered (b,h,q) for L2 locality.
__global__ __launch_bounds__(256) void k_sample(float* __restrict__ out) {
    int warp = blockIdx.x * 8 + (threadIdx.x >> 5);
    int d    = threadIdx.x & 31;
    if (warp >= BS * NH * LQ) return;

    int q  = warp % LQ;
    int bh = warp / LQ;       // b*NH + h
    int b  = bh / NH;
    int h  = bh % NH;
    int gm = b * LQ + q;

    const __half* __restrict__ vt = g_valueT + (size_t)bh * TOTAL * HD;
    const float* locp  = g_loc  + ((size_t)gm * NH + h) * SUMP * 2;
    const float* attnp = g_attn + ((size_t)gm * NH + h) * SUMP;

    float acc = 0.f;
    #pragma unroll
    for (int p = 0; p < SUMP; p++) {
        int lvl = p >> 2;
        int Hh = c_lvl_H[lvl], Ww = c_lvl_W[lvl];
        int st = c_lvl_start[lvl];
        float a  = attnp[p];
        float lx = locp[p * 2 + 0];
        float ly = locp[p * 2 + 1];
        // grid = 2*loc-1; pixel = loc*W - 0.5
        float x = lx * (float)Ww - 0.5f;
        float y = ly * (float)Hh - 0.5f;
        float fx0 = floorf(x), fy0 = floorf(y);
        int ix0 = (int)fx0, iy0 = (int)fy0;
        float fx = x - fx0, fy = y - fy0;
        int ix1 = ix0 + 1, iy1 = iy0 + 1;

        bool vx0 = (ix0 >= 0) & (ix0 < Ww);
        bool vx1 = (ix1 >= 0) & (ix1 < Ww);
        bool vy0 = (iy0 >= 0) & (iy0 < Hh);
        bool vy1 = (iy1 >= 0) & (iy1 < Hh);

        float v00 = (vx0 & vy0) ? __half2float(__ldg(vt + (size_t)(st + iy0 * Ww + ix0) * HD + d)) : 0.f;
        float v10 = (vx1 & vy0) ? __half2float(__ldg(vt + (size_t)(st + iy0 * Ww + ix1) * HD + d)) : 0.f;
        float v01 = (vx0 & vy1) ? __half2float(__ldg(vt + (size_t)(st + iy1 * Ww + ix0) * HD + d)) : 0.f;
        float v11 = (vx1 & vy1) ? __half2float(__ldg(vt + (size_t)(st + iy1 * Ww + ix1) * HD + d)) : 0.f;

        float bil = v00 * (1.f - fx) * (1.f - fy)
                  + v10 * fx * (1.f - fy)
                  + v01 * (1.f - fx) * fy
                  + v11 * fx * fy;
        acc = fmaf(a, bil, acc);
    }
    out[(size_t)gm * EMB + h * HD + d] = acc;
}

// ================= launch =================
extern "C" void kernel_launch(void* const* d_in, const int* in_sizes, int n_in,
                              void* d_out, int out_size) {
    const float* query  = (const float*)d_in[0];
    const float* refpts = (const float*)d_in[1];
    const float* value  = (const float*)d_in[2];
    // d_in[3] = value_spatial_shapes (int32) -- constants hardcoded
    const float* W_off  = (const float*)d_in[4];
    const float* b_off  = (const float*)d_in[5];
    const float* W_attn = (const float*)d_in[6];
    const float* b_attn = (const float*)d_in[7];
    float* out = (float*)d_out;

    dim3 tgrid((TOTAL + 31) / 32, BS * NH);
    k_transpose<<<tgrid, dim3(256)>>>(value);

    k_proj<<<MROWS / 32, 384>>>(query, refpts, W_off, b_off, W_attn, b_attn);

    int nwarps = BS * NH * LQ;                // 76800
    k_sample<<<(nwarps + 7) / 8, 256>>>(out);
}

// round 3
// speedup vs baseline: 1.8866x; 1.5415x over previous
#include <cuda_runtime.h>
#include <cuda_fp16.h>
#include <math.h>

// ---------------- problem constants ----------------
#define BS    32
#define LQ    300
#define NH    8
#define HD    32
#define EMB   (NH*HD)        // 256
#define NLVL  4
#define NPTS  4
#define SUMP  (NLVL*NPTS)    // 16
#define TOTAL 8500
#define MROWS (BS*LQ)        // 9600

__device__ __constant__ int c_lvl_start[NLVL] = {0, 6400, 8000, 8400};
__device__ __constant__ int c_lvl_H[NLVL]     = {80, 40, 20, 10};
__device__ __constant__ int c_lvl_W[NLVL]     = {80, 40, 20, 10};

// ---------------- scratch ----------------
__device__ __half g_valueT[(size_t)BS*NH*TOTAL*HD];    // ~139 MB, [b,h,s,d] fp16
__device__ float  g_attn[(size_t)MROWS*NH*SUMP];       // linear: gm*128 + (h*16+p)
__device__ float  g_loc[(size_t)MROWS*NH*SUMP*2];      // linear: gm*256 + (h*32+p*2+comp)

// ---------------- f32x2 packed helpers (sm_103a) ----------------
typedef unsigned long long ull;
__device__ __forceinline__ ull pack2(float lo, float hi) {
    ull r; asm("mov.b64 %0, {%1, %2};" : "=l"(r) : "f"(lo), "f"(hi)); return r;
}
__device__ __forceinline__ void unpack2(ull v, float& lo, float& hi) {
    asm("mov.b64 {%0, %1}, %2;" : "=f"(lo), "=f"(hi) : "l"(v));
}
__device__ __forceinline__ void ffma2(ull& d, ull a, ull b) {
    asm("fma.rn.f32x2 %0, %1, %2, %0;" : "+l"(d) : "l"(a), "l"(b));
}

// ================= kernel 1: value transpose fp32 [b,h,d,s] -> fp16 [b,h,s,d] =================
// 32 d x 64 s tiles, float4 reads, padded smem, half2 writes.
__global__ __launch_bounds__(256) void k_transpose(const float* __restrict__ value) {
    __shared__ float tile[32 * 68];      // row stride 68 floats (16B aligned, padded)
    int bh = blockIdx.y;
    int s0 = blockIdx.x * 64;
    int t  = threadIdx.x;
    int sx4 = t & 15;                    // float4 index along s (16 * 4 = 64)
    int dh  = t >> 4;                    // 0..15

    const float* src = value + (size_t)bh * HD * TOTAL;
    __half* dst = g_valueT + (size_t)bh * TOTAL * HD;

    int sbase = s0 + sx4 * 4;
    #pragma unroll
    for (int i = 0; i < 2; i++) {
        int d = dh + i * 16;
        float4 v;
        if (sbase + 3 < TOTAL) {
            v = *(const float4*)(src + (size_t)d * TOTAL + sbase);
        } else {
            v.x = (sbase + 0 < TOTAL) ? src[(size_t)d * TOTAL + sbase + 0] : 0.f;
            v.y = (sbase + 1 < TOTAL) ? src[(size_t)d * TOTAL + sbase + 1] : 0.f;
            v.z = (sbase + 2 < TOTAL) ? src[(size_t)d * TOTAL + sbase + 2] : 0.f;
            v.w = (sbase + 3 < TOTAL) ? src[(size_t)d * TOTAL + sbase + 3] : 0.f;
        }
        *(float4*)(tile + d * 68 + sx4 * 4) = v;
    }
    __syncthreads();
    // write: 64 rows x 16 half2 entities = 1024; 4 per thread
    #pragma unroll
    for (int i = 0; i < 4; i++) {
        int e  = t + i * 256;
        int r  = e >> 4;                 // local s row 0..63
        int dp = e & 15;                 // d pair
        int s  = s0 + r;
        if (s < TOTAL) {
            float lo = tile[(2*dp)     * 68 + r];
            float hi = tile[(2*dp + 1) * 68 + r];
            *((__half2*)(dst + (size_t)s * HD) + dp) = __floats2half2_rn(lo, hi);
        }
    }
}

// ================= kernel 2: projections + softmax + locations =================
// Block = 32 query rows, 192 threads. Thread = (rg 0..3, cg 0..47):
// rows rg*8..+7 (4 f32x2 row-pairs), cols cg*8..+7.
// cols 0..255 -> W_off (locations); cols 256..383 -> W_attn (softmax).
__global__ __launch_bounds__(192) void k_proj(const float* __restrict__ query,
                                              const float* __restrict__ refpts,
                                              const float* __restrict__ W_off,
                                              const float* __restrict__ b_off,
                                              const float* __restrict__ W_attn,
                                              const float* __restrict__ b_attn) {
    __shared__ float qs[EMB * 34];       // [k][row], row stride 34 (LDS.64-aligned)
    int m0 = blockIdx.x * 32;
    int t  = threadIdx.x;

    for (int idx = t; idx < 32 * EMB; idx += 192) {
        int row = idx >> 8;
        int k   = idx & 255;
        qs[k * 34 + row] = query[(size_t)m0 * EMB + idx];
    }
    __syncthreads();

    int rg   = t / 48;
    int cg   = t % 48;
    int col0 = cg * 8;
    bool is_off = (col0 < EMB);
    const float* Wp = is_off ? (W_off + col0) : (W_attn + (col0 - EMB));
    int ld = is_off ? EMB : (NH * SUMP);

    ull acc[4][8];
    #pragma unroll
    for (int j = 0; j < 4; j++)
        #pragma unroll
        for (int c = 0; c < 8; c++) acc[j][c] = 0ull;

    #pragma unroll 2
    for (int k = 0; k < EMB; k++) {
        ull q2[4];
        #pragma unroll
        for (int j = 0; j < 4; j++)
            q2[j] = *(const ull*)(qs + k * 34 + rg * 8 + 2 * j);
        float4 w0 = *(const float4*)(Wp + (size_t)k * ld);
        float4 w1 = *(const float4*)(Wp + (size_t)k * ld + 4);
        float w[8] = {w0.x, w0.y, w0.z, w0.w, w1.x, w1.y, w1.z, w1.w};
        #pragma unroll
        for (int c = 0; c < 8; c++) {
            ull w2 = pack2(w[c], w[c]);
            #pragma unroll
            for (int j = 0; j < 4; j++)
                ffma2(acc[j][c], q2[j], w2);
        }
    }

    float bias[8];
    {
        const float* bp = is_off ? (b_off + col0) : (b_attn + (col0 - EMB));
        #pragma unroll
        for (int c = 0; c < 8; c++) bias[c] = bp[c];
    }

    if (is_off) {
        #pragma unroll
        for (int j = 0; j < 4; j++) {
            #pragma unroll
            for (int par = 0; par < 2; par++) {
                int r  = rg * 8 + 2 * j + par;
                int gm = m0 + r;
                float4 rp = *(const float4*)(refpts + (size_t)gm * 4);
                float4 o0, o1;
                float ov[8];
                #pragma unroll
                for (int c = 0; c < 8; c++) {
                    float lo, hi; unpack2(acc[j][c], lo, hi);
                    float v = (par ? hi : lo) + bias[c];
                    int comp = (col0 + c) & 1;
                    float rxy = comp ? rp.y : rp.x;
                    float rwh = comp ? rp.w : rp.z;
                    ov[c] = fmaf(v * 0.125f, rwh, rxy);  // (1/NPTS)*0.5
                }
                o0 = make_float4(ov[0], ov[1], ov[2], ov[3]);
                o1 = make_float4(ov[4], ov[5], ov[6], ov[7]);
                *(float4*)(g_loc + (size_t)gm * 256 + col0)     = o0;
                *(float4*)(g_loc + (size_t)gm * 256 + col0 + 4) = o1;
            }
        }
    } else {
        int hidx = col0 - EMB;                       // 0..120, step 8
        unsigned mask16 = 0xFFFFu << (t & 16);
        #pragma unroll
        for (int j = 0; j < 4; j++) {
            #pragma unroll
            for (int par = 0; par < 2; par++) {
                int r  = rg * 8 + 2 * j + par;
                int gm = m0 + r;
                float v[8];
                float mx = -1e30f;
                #pragma unroll
                for (int c = 0; c < 8; c++) {
                    float lo, hi; unpack2(acc[j][c], lo, hi);
                    v[c] = (par ? hi : lo) + bias[c];
                    mx = fmaxf(mx, v[c]);
                }
                mx = fmaxf(mx, __shfl_xor_sync(mask16, mx, 1));
                float s = 0.f;
                #pragma unroll
                for (int c = 0; c < 8; c++) { v[c] = __expf(v[c] - mx); s += v[c]; }
                s += __shfl_xor_sync(mask16, s, 1);
                float inv = __frcp_rn(s);
                float4 a0 = make_float4(v[0]*inv, v[1]*inv, v[2]*inv, v[3]*inv);
                float4 a1 = make_float4(v[4]*inv, v[5]*inv, v[6]*inv, v[7]*inv);
                *(float4*)(g_attn + (size_t)gm * 128 + hidx)     = a0;
                *(float4*)(g_attn + (size_t)gm * 128 + hidx + 4) = a1;
            }
        }
    }
}

// ================= kernel 3: bilinear sampling + weighted sum =================
// Warp = 2 queries (half-warp each); lane = channel pair (half2 taps, f32x2 math).
#define QPAIRS (LQ/2)   // 150
__global__ __launch_bounds__(256) void k_sample(float* __restrict__ out) {
    int warp = blockIdx.x * 8 + (threadIdx.x >> 5);
    if (warp >= BS * NH * QPAIRS) return;
    int lane = threadIdx.x & 31;
    int half = lane >> 4;
    int l    = lane & 15;

    int qp = warp % QPAIRS;
    int bh = warp / QPAIRS;
    int q  = qp * 2 + half;
    int b  = bh >> 3;
    int h  = bh & 7;
    int gm = b * LQ + q;

    const __half2* __restrict__ vt2 =
        (const __half2*)(g_valueT + (size_t)bh * TOTAL * HD);
    const float* locp  = g_loc  + (size_t)gm * 256 + h * 32;
    const float* attnp = g_attn + (size_t)gm * 128 + h * 16;

    // stage loc (32 floats) and attn (16 floats) across 16 lanes
    float locA = locp[l];
    float locB = locp[l + 16];
    float aw   = attnp[l];

    int src0 = lane & 16;
    const unsigned FULL = 0xffffffffu;
    __half2 z2 = __float2half2_rn(0.f);

    ull acc2 = 0ull;
    #pragma unroll
    for (int p = 0; p < SUMP; p++) {
        int lvl = p >> 2;
        int Hh = c_lvl_H[lvl], Ww = c_lvl_W[lvl];
        int st = c_lvl_start[lvl];

        float lx = __shfl_sync(FULL, (2*p < 16)   ? locA : locB, src0 + ((2*p)   & 15));
        float ly = __shfl_sync(FULL, (2*p+1 < 16) ? locA : locB, src0 + ((2*p+1) & 15));
        float a  = __shfl_sync(FULL, aw, src0 + p);

        float x = lx * (float)Ww - 0.5f;
        float y = ly * (float)Hh - 0.5f;
        float fx0 = floorf(x), fy0 = floorf(y);
        int ix0 = (int)fx0, iy0 = (int)fy0;
        float fx = x - fx0, fy = y - fy0;
        int ix1 = ix0 + 1, iy1 = iy0 + 1;

        bool vx0 = (ix0 >= 0) & (ix0 < Ww);
        bool vx1 = (ix1 >= 0) & (ix1 < Ww);
        bool vy0 = (iy0 >= 0) & (iy0 < Hh);
        bool vy1 = (iy1 >= 0) & (iy1 < Hh);

        __half2 h00 = (vx0 & vy0) ? __ldg(vt2 + (size_t)(st + iy0*Ww + ix0) * 16 + l) : z2;
        __half2 h10 = (vx1 & vy0) ? __ldg(vt2 + (size_t)(st + iy0*Ww + ix1) * 16 + l) : z2;
        __half2 h01 = (vx0 & vy1) ? __ldg(vt2 + (size_t)(st + iy1*Ww + ix0) * 16 + l) : z2;
        __half2 h11 = (vx1 & vy1) ? __ldg(vt2 + (size_t)(st + iy1*Ww + ix1) * 16 + l) : z2;

        float w00 = (1.f - fx) * (1.f - fy);
        float w10 = fx * (1.f - fy);
        float w01 = (1.f - fx) * fy;
        float w11 = fx * fy;

        float2 f00 = __half22float2(h00);
        float2 f10 = __half22float2(h10);
        float2 f01 = __half22float2(h01);
        float2 f11 = __half22float2(h11);

        ull bil2 = 0ull;
        ffma2(bil2, pack2(f00.x, f00.y), pack2(w00, w00));
        ffma2(bil2, pack2(f10.x, f10.y), pack2(w10, w10));
        ffma2(bil2, pack2(f01.x, f01.y), pack2(w01, w01));
        ffma2(bil2, pack2(f11.x, f11.y), pack2(w11, w11));
        ffma2(acc2, bil2, pack2(a, a));
    }
    float lo, hi; unpack2(acc2, lo, hi);
    *(float2*)(out + (size_t)gm * EMB + h * HD + 2 * l) = make_float2(lo, hi);
}

// ================= launch =================
extern "C" void kernel_launch(void* const* d_in, const int* in_sizes, int n_in,
                              void* d_out, int out_size) {
    const float* query  = (const float*)d_in[0];
    const float* refpts = (const float*)d_in[1];
    const float* value  = (const float*)d_in[2];
    const float* W_off  = (const float*)d_in[4];
    const float* b_off  = (const float*)d_in[5];
    const float* W_attn = (const float*)d_in[6];
    const float* b_attn = (const float*)d_in[7];
    float* out = (float*)d_out;

    dim3 tgrid((TOTAL + 63) / 64, BS * NH);
    k_transpose<<<tgrid, 256>>>(value);

    k_proj<<<MROWS / 32, 192>>>(query, refpts, W_off, b_off, W_attn, b_attn);

    int nwarps = BS * NH * QPAIRS;            // 38400
    k_sample<<<(nwarps + 7) / 8, 256>>>(out);
}